// round 2
// baseline (speedup 1.0000x reference)
#include <cuda_runtime.h>
#include <cuda_bf16.h>
#include <stdint.h>

#define BG    8      // graphs
#define NPER  256    // nodes per graph
#define NN    2048   // total nodes
#define FF    512    // features
#define EE    65536  // edges
#define KSEL  204    // kept per graph
#define NK    1632   // pooled nodes
#define KHOP  3

#define OUT_FEATP_OFF 0
#define OUT_W_OFF     (NK*FF)                 // 835584
#define OUT_PERM_OFF  (NK*FF + NK*NK)         // 3499008
#define OUT_TOTAL     (NK*FF + NK*NK + NK)    // 3500640

// ---------------- scratch (device globals; no allocation allowed) ----------
__device__ float  d_A[BG*NPER*NPER];   // adjacency (weighted, incl self loops)
__device__ float  d_T[BG*NPER*NPER];   // temp: Bmat (agg) then A@A (khop)
__device__ float  d_deg_out[NN];
__device__ float  d_deg_in[NN];
__device__ double d_score[NN];         // DOUBLE: top-k rank must match truth
__device__ int    d_perm_local[BG*KSEL];
__device__ float  d_ssrc[NK];
__device__ float  d_sdst[NK];
__device__ float  d_maxT[KHOP];

// ---------------- init: zero everything that gets accumulated -------------
__global__ void k_init(float* out) {
    int64_t i = (int64_t)blockIdx.x * blockDim.x + threadIdx.x;
    int64_t stride = (int64_t)gridDim.x * blockDim.x;
    for (int64_t t = i; t < OUT_TOTAL; t += stride) out[t] = 0.0f;
    for (int64_t t = i; t < (int64_t)BG*NPER*NPER; t += stride) d_A[t] = 0.0f;
    for (int64_t t = i; t < NN; t += stride) {
        d_deg_out[t] = 0.0f; d_deg_in[t] = 0.0f; d_score[t] = 0.0;
    }
    if (i < KHOP) d_maxT[i] = 0.0f;
}

// ---------------- scatter edges into dense A + degree counts --------------
__global__ void k_scatter(const float* __restrict__ ef,
                          const int* __restrict__ row,
                          const int* __restrict__ col) {
    int e = blockIdx.x * blockDim.x + threadIdx.x;
    if (e >= EE) return;
    int r = row[e], c = col[e];
    int g = r >> 8;
    int rl = r & 255, cl = c & 255;
    atomicAdd(&d_A[(g << 16) + (rl << 8) + cl], ef[e]);
    atomicAdd(&d_deg_out[r], 1.0f);
    atomicAdd(&d_deg_in[c], 1.0f);
}

// ---------------- Bmat[c][r] = (r!=c) * A[r][c] * srcn[r] * dstn[c] -------
__global__ void k_bmat() {
    int idx = blockIdx.x * blockDim.x + threadIdx.x;
    if (idx >= BG*NPER*NPER) return;
    int g = idx >> 16;
    int c = (idx >> 8) & 255;
    int r = idx & 255;
    float v = 0.0f;
    if (r != c) {
        float a = d_A[(g << 16) + (r << 8) + c];
        float sn = 1.0f / sqrtf(fmaxf(d_deg_out[g*NPER + r], 1.0f));
        float dn = 1.0f / sqrtf(fmaxf(d_deg_in[g*NPER + c], 1.0f));
        v = a * sn * dn;
    }
    d_T[idx] = v;   // Bmat stored in d_T
}

// ------------- agg = Bmat @ feat_g fused with score epilogue --------------
// grid: (FF/64, NPER/64, BG), block: 256. 64x64 tile, 4x4 per thread.
__global__ void k_aggscore(const float* __restrict__ feat) {
    int g = blockIdx.z;
    int fBase = blockIdx.x * 64;
    int cBase = blockIdx.y * 64;
    const float* Bm = d_T + (g << 16);
    const float* fg = feat + (int64_t)g * NPER * FF;

    __shared__ float  As[64][17];
    __shared__ float  Bs[16][65];
    __shared__ double srow[64];
    int tid = threadIdx.x, tx = tid & 15, ty = tid >> 4;
    if (tid < 64) srow[tid] = 0.0;

    float acc[4][4] = {};
    for (int k0 = 0; k0 < NPER; k0 += 16) {
        #pragma unroll
        for (int t = 0; t < 4; t++) {
            int li = tid + t * 256;
            int r = li >> 4, kk = li & 15;
            As[r][kk] = Bm[(cBase + r) * NPER + k0 + kk];
        }
        #pragma unroll
        for (int t = 0; t < 4; t++) {
            int li = tid + t * 256;
            int kk = li >> 6, c = li & 63;
            Bs[kk][c] = fg[(k0 + kk) * FF + fBase + c];
        }
        __syncthreads();
        #pragma unroll
        for (int kk = 0; kk < 16; kk++) {
            float af[4], bf[4];
            #pragma unroll
            for (int i = 0; i < 4; i++) af[i] = As[ty*4 + i][kk];
            #pragma unroll
            for (int j = 0; j < 4; j++) bf[j] = Bs[kk][tx*4 + j];
            #pragma unroll
            for (int i = 0; i < 4; i++)
                #pragma unroll
                for (int j = 0; j < 4; j++) acc[i][j] += af[i] * bf[j];
        }
        __syncthreads();
    }
    #pragma unroll
    for (int i = 0; i < 4; i++) {
        int c = cBase + ty*4 + i;
        double p = 0.0;
        #pragma unroll
        for (int j = 0; j < 4; j++) {
            float fv = fg[c * FF + fBase + tx*4 + j];
            p += (double)fabsf(fv - acc[i][j]);
        }
        atomicAdd(&srow[ty*4 + i], p);
    }
    __syncthreads();
    if (tid < 64) atomicAdd(&d_score[g*NPER + cBase + tid], srow[tid]);
}

// ---------------- top-k per graph via bitonic sort (double keys) ----------
__global__ void k_topk(float* __restrict__ out_perm) {
    int g = blockIdx.x;
    int tid = threadIdx.x;
    __shared__ double sk[256];
    __shared__ int    si[256];
    sk[tid] = d_score[g*NPER + tid];
    si[tid] = tid;
    __syncthreads();
    for (int k2 = 2; k2 <= 256; k2 <<= 1) {
        for (int jj = k2 >> 1; jj > 0; jj >>= 1) {
            int ixj = tid ^ jj;
            if (ixj > tid) {
                double a = sk[tid], b = sk[ixj];
                int ia = si[tid], ib = si[ixj];
                // "a first" in descending order (tie -> lower index first)
                bool aFirst = (a > b) || (a == b && ia < ib);
                bool desc = ((tid & k2) == 0);
                bool doswap = desc ? !aFirst : aFirst;
                if (doswap) { sk[tid] = b; sk[ixj] = a; si[tid] = ib; si[ixj] = ia; }
            }
            __syncthreads();
        }
    }
    if (tid < KSEL) {
        d_perm_local[g*KSEL + tid] = si[tid];
        out_perm[g*KSEL + tid] = (float)(g*NPER + si[tid]);
    }
}

// -------------- gather feat_p + attention scores s_src/s_dst --------------
__global__ void k_gather(const float* __restrict__ feat,
                         const float* __restrict__ att,
                         float* __restrict__ out_featp) {
    int i = blockIdx.x;              // pooled idx 0..NK-1
    int g = i / KSEL;
    int node = g*NPER + d_perm_local[i];
    int tid = threadIdx.x;
    const float* fr = feat + (int64_t)node * FF;
    float* orow = out_featp + (int64_t)i * FF;
    double a1 = 0.0, a2 = 0.0;
    for (int f = tid; f < FF; f += 128) {
        float v = fr[f];
        orow[f] = v;
        a1 += (double)v * (double)att[f];
        a2 += (double)v * (double)att[FF + f];
    }
    #pragma unroll
    for (int off = 16; off > 0; off >>= 1) {
        a1 += __shfl_down_sync(0xffffffffu, a1, off);
        a2 += __shfl_down_sync(0xffffffffu, a2, off);
    }
    __shared__ double s1[4], s2[4];
    int w = tid >> 5, l = tid & 31;
    if (l == 0) { s1[w] = a1; s2[w] = a2; }
    __syncthreads();
    if (tid == 0) {
        d_ssrc[i] = (float)(s1[0] + s1[1] + s1[2] + s1[3]);
        d_sdst[i] = (float)(s2[0] + s2[1] + s2[2] + s2[3]);
    }
}

// ---------------- khop: T = A@A per block + global max --------------------
// grid: (NPER/64, NPER/64, BG), block 256
__global__ void k_mm(int iter) {
    int g = blockIdx.z;
    int cBase = blockIdx.x * 64;
    int rBase = blockIdx.y * 64;
    const float* Ag = d_A + (g << 16);
    float* Tg = d_T + (g << 16);

    __shared__ float As[64][17];
    __shared__ float Bs[16][65];
    int tid = threadIdx.x, tx = tid & 15, ty = tid >> 4;
    float acc[4][4] = {};
    for (int k0 = 0; k0 < NPER; k0 += 16) {
        #pragma unroll
        for (int t = 0; t < 4; t++) {
            int li = tid + t * 256;
            int r = li >> 4, kk = li & 15;
            As[r][kk] = Ag[(rBase + r) * NPER + k0 + kk];
        }
        #pragma unroll
        for (int t = 0; t < 4; t++) {
            int li = tid + t * 256;
            int kk = li >> 6, c = li & 63;
            Bs[kk][c] = Ag[(k0 + kk) * NPER + cBase + c];
        }
        __syncthreads();
        #pragma unroll
        for (int kk = 0; kk < 16; kk++) {
            float af[4], bf[4];
            #pragma unroll
            for (int i = 0; i < 4; i++) af[i] = As[ty*4 + i][kk];
            #pragma unroll
            for (int j = 0; j < 4; j++) bf[j] = Bs[kk][tx*4 + j];
            #pragma unroll
            for (int i = 0; i < 4; i++)
                #pragma unroll
                for (int j = 0; j < 4; j++) acc[i][j] += af[i] * bf[j];
        }
        __syncthreads();
    }
    float m = 0.0f;
    #pragma unroll
    for (int i = 0; i < 4; i++)
        #pragma unroll
        for (int j = 0; j < 4; j++) {
            float v = acc[i][j];
            Tg[(rBase + ty*4 + i) * NPER + cBase + tx*4 + j] = v;
            m = fmaxf(m, v);
        }
    // block max reduce (values are nonnegative)
    __shared__ float sm[256];
    sm[tid] = m;
    __syncthreads();
    for (int off = 128; off > 0; off >>= 1) {
        if (tid < off) sm[tid] = fmaxf(sm[tid], sm[tid + off]);
        __syncthreads();
    }
    if (tid == 0)
        atomicMax((unsigned int*)&d_maxT[iter], __float_as_uint(sm[0]));
}

__global__ void k_axpy(int iter) {
    float s = 1e-5f / d_maxT[iter];
    int64_t i = (int64_t)blockIdx.x * blockDim.x + threadIdx.x;
    int64_t stride = (int64_t)gridDim.x * blockDim.x;
    for (int64_t t = i; t < (int64_t)BG*NPER*NPER; t += stride)
        d_A[t] += d_T[t] * s;
}

// ---------------- sparsemax per dst column (in-block only) ----------------
// grid: (KSEL, BG), block 256
__global__ void k_sparsemax(float* __restrict__ outw) {
    int jj = blockIdx.x;   // pooled column within graph
    int g  = blockIdx.y;
    int tid = threadIdx.x;
    __shared__ float zorig[256], zs[256], cs[256];

    int plj = d_perm_local[g*KSEL + jj];
    float sdstj = d_sdst[g*KSEL + jj];

    float z = -1e9f;
    bool maskv = false;
    if (tid < KSEL) {
        int pli = d_perm_local[g*KSEL + tid];
        float a = d_A[(g << 16) + (pli << 8) + plj];
        maskv = (a != 0.0f) || (tid == jj);
        if (maskv) {
            float raw = d_ssrc[g*KSEL + tid] + sdstj;
            float lr = raw > 0.0f ? raw : 0.2f * raw;
            z = lr + a;    // LAMB = 1
        }
    }
    zorig[tid] = z;
    zs[tid] = z;
    __syncthreads();

    // bitonic sort descending (values only)
    for (int k2 = 2; k2 <= 256; k2 <<= 1) {
        for (int j2 = k2 >> 1; j2 > 0; j2 >>= 1) {
            int ixj = tid ^ j2;
            if (ixj > tid) {
                float a = zs[tid], b = zs[ixj];
                bool desc = ((tid & k2) == 0);
                if (desc ? (b > a) : (a > b)) { zs[tid] = b; zs[ixj] = a; }
            }
            __syncthreads();
        }
    }
    cs[tid] = zs[tid];
    __syncthreads();
    // inclusive scan (Hillis-Steele)
    for (int off = 1; off < 256; off <<= 1) {
        float v = (tid >= off) ? cs[tid - off] : 0.0f;
        __syncthreads();
        cs[tid] += v;
        __syncthreads();
    }
    bool cond = (1.0f + (float)(tid + 1) * zs[tid]) > cs[tid];
    int ksel = __syncthreads_count(cond);
    float tau = (cs[ksel - 1] - 1.0f) / (float)ksel;
    if (tid < KSEL) {
        float wv = maskv ? fmaxf(zorig[tid] - tau, 0.0f) : 0.0f;
        outw[(int64_t)(g*KSEL + tid) * NK + (g*KSEL + jj)] = wv;
    }
}

// ---------------------------------------------------------------------------
extern "C" void kernel_launch(void* const* d_in, const int* in_sizes, int n_in,
                              void* d_out, int out_size) {
    const float* feat = (const float*)d_in[0];
    const float* ef   = (const float*)d_in[1];
    const float* att  = (const float*)d_in[2];
    const int*   row  = (const int*)d_in[3];
    const int*   col  = (const int*)d_in[4];
    float* out = (float*)d_out;

    k_init<<<512, 256>>>(out);
    k_scatter<<<EE/256, 256>>>(ef, row, col);
    k_bmat<<<(BG*NPER*NPER)/256, 256>>>();
    k_aggscore<<<dim3(FF/64, NPER/64, BG), 256>>>(feat);
    k_topk<<<BG, 256>>>(out + OUT_PERM_OFF);
    k_gather<<<NK, 128>>>(feat, att, out + OUT_FEATP_OFF);
    for (int it = 0; it < KHOP; it++) {
        k_mm<<<dim3(NPER/64, NPER/64, BG), 256>>>(it);
        k_axpy<<<512, 256>>>(it);
    }
    k_sparsemax<<<dim3(KSEL, BG), 256>>>(out + OUT_W_OFF);
}

// round 3
// speedup vs baseline: 1.3528x; 1.3528x over previous
#include <cuda_runtime.h>
#include <cuda_bf16.h>
#include <stdint.h>

#define BG    8      // graphs
#define NPER  256    // nodes per graph
#define NN    2048   // total nodes
#define FF    512    // features
#define EE    65536  // edges
#define KSEL  204    // kept per graph
#define NK    1632   // pooled nodes
#define KHOP  3

#define OUT_FEATP_OFF 0
#define OUT_W_OFF     (NK*FF)                 // 835584
#define OUT_PERM_OFF  (NK*FF + NK*NK)         // 3499008

#define FFMA2(d,a,b) asm("fma.rn.f32x2 %0, %1, %2, %0;" : "+l"(d) : "l"(a), "l"(b))

__device__ __forceinline__ unsigned long long pack_dup(float x) {
    unsigned long long p;
    unsigned int u = __float_as_uint(x);
    asm("mov.b64 %0, {%1, %2};" : "=l"(p) : "r"(u), "r"(u));
    return p;
}
__device__ __forceinline__ float2 unpk(unsigned long long v) {
    unsigned int lo, hi;
    asm("mov.b64 {%0, %1}, %2;" : "=r"(lo), "=r"(hi) : "l"(v));
    return make_float2(__uint_as_float(lo), __uint_as_float(hi));
}

// ---------------- scratch (device globals; no allocation allowed) ----------
__device__ float  d_A[BG*NPER*NPER];
__device__ float  d_T[BG*NPER*NPER];
__device__ float  d_deg_out[NN];
__device__ float  d_deg_in[NN];
__device__ float  d_srcn[NN];
__device__ float  d_dstn[NN];
__device__ double d_score[NN];         // double: top-k rank must match truth
__device__ int    d_perm_local[BG*KSEL];
__device__ float  d_ssrc[NK];
__device__ float  d_sdst[NK];
__device__ float  d_maxT[KHOP];

// ---------------- init ---------------------------------------------------
__global__ void k_init(float* out) {
    int64_t i = (int64_t)blockIdx.x * blockDim.x + threadIdx.x;
    int64_t stride = (int64_t)gridDim.x * blockDim.x;
    float* w = out + OUT_W_OFF;
    for (int64_t t = i; t < (int64_t)NK*NK; t += stride) w[t] = 0.0f;
    for (int64_t t = i; t < (int64_t)BG*NPER*NPER; t += stride) d_A[t] = 0.0f;
    for (int64_t t = i; t < NN; t += stride) {
        d_deg_out[t] = 0.0f; d_deg_in[t] = 0.0f; d_score[t] = 0.0;
    }
    if (i < KHOP) d_maxT[i] = 0.0f;
}

// ---------------- scatter edges + degrees --------------------------------
__global__ void k_scatter(const float* __restrict__ ef,
                          const int* __restrict__ row,
                          const int* __restrict__ col) {
    int e = blockIdx.x * blockDim.x + threadIdx.x;
    if (e >= EE) return;
    int r = row[e], c = col[e];
    int g = r >> 8;
    atomicAdd(&d_A[(g << 16) + ((r & 255) << 8) + (c & 255)], ef[e]);
    atomicAdd(&d_deg_out[r], 1.0f);
    atomicAdd(&d_deg_in[c], 1.0f);
}

__global__ void k_norm() {
    int i = blockIdx.x * blockDim.x + threadIdx.x;
    if (i >= NN) return;
    d_srcn[i] = 1.0f / sqrtf(fmaxf(d_deg_out[i], 1.0f));
    d_dstn[i] = 1.0f / sqrtf(fmaxf(d_deg_in[i], 1.0f));
}

// ------------- agg = (sym-norm A^T) @ feat fused with score epilogue ------
// grid (FF/64, NPER/64, BG), block 256. 64x64 tile, 4(m)x4(n)/thread, f32x2.
__global__ void __launch_bounds__(256) k_aggscore(const float* __restrict__ feat) {
    const int g = blockIdx.z;
    const int fBase = blockIdx.x * 64;
    const int cBase = blockIdx.y * 64;
    const int tid = threadIdx.x, tx = tid & 15, ty = tid >> 4;
    __shared__ float As[2][16][68];
    __shared__ float Bs[2][16][68];
    const float* Ag = d_A + (g << 16);
    const float* fg = feat + (g << 17);

    float4 ra, rb; float sc; int rk = 0;
    // fetch stage s into regs
    auto fetch = [&](int s) {
        int k = s * 16 + ty;
        rk = k;
        ra = *(const float4*)(Ag + k * 256 + cBase + tx * 4);
        sc = d_srcn[g * 256 + k];
        rb = *(const float4*)(fg + k * 512 + fBase + tx * 4);
    };
    auto stash = [&](int b) {
        int c0 = cBase + tx * 4;
        float4 v;
        v.x = (rk == c0 + 0) ? 0.0f : ra.x * sc;
        v.y = (rk == c0 + 1) ? 0.0f : ra.y * sc;
        v.z = (rk == c0 + 2) ? 0.0f : ra.z * sc;
        v.w = (rk == c0 + 3) ? 0.0f : ra.w * sc;
        *(float4*)&As[b][ty][tx * 4] = v;
        *(float4*)&Bs[b][ty][tx * 4] = rb;
    };

    unsigned long long acc[4][2] = {};
    fetch(0); stash(0); __syncthreads();
    #pragma unroll 1
    for (int s = 0; s < 16; s++) {
        if (s < 15) fetch(s + 1);
        int b = s & 1;
        #pragma unroll
        for (int kk = 0; kk < 16; kk++) {
            const float4 a4 = *(const float4*)&As[b][kk][ty * 4];
            const ulonglong2 b2 = *(const ulonglong2*)&Bs[b][kk][tx * 4];
            unsigned long long pa;
            pa = pack_dup(a4.x); FFMA2(acc[0][0], pa, b2.x); FFMA2(acc[0][1], pa, b2.y);
            pa = pack_dup(a4.y); FFMA2(acc[1][0], pa, b2.x); FFMA2(acc[1][1], pa, b2.y);
            pa = pack_dup(a4.z); FFMA2(acc[2][0], pa, b2.x); FFMA2(acc[2][1], pa, b2.y);
            pa = pack_dup(a4.w); FFMA2(acc[3][0], pa, b2.x); FFMA2(acc[3][1], pa, b2.y);
        }
        if (s < 15) stash((s + 1) & 1);
        __syncthreads();
    }

    // epilogue: agg = dstn[c] * acc; p = sum |feat - agg| (double), reduce over tx
    #pragma unroll
    for (int i = 0; i < 4; i++) {
        int c = cBase + ty * 4 + i;
        float dn = d_dstn[g * 256 + c];
        float2 lo = unpk(acc[i][0]);
        float2 hi = unpk(acc[i][1]);
        float4 f4 = *(const float4*)(fg + c * 512 + fBase + tx * 4);
        double p = (double)fabsf(f4.x - dn * lo.x)
                 + (double)fabsf(f4.y - dn * lo.y)
                 + (double)fabsf(f4.z - dn * hi.x)
                 + (double)fabsf(f4.w - dn * hi.y);
        #pragma unroll
        for (int off = 8; off > 0; off >>= 1)
            p += __shfl_down_sync(0xffffffffu, p, off, 16);
        if (tx == 0) atomicAdd(&d_score[g * 256 + c], p);
    }
}

// ---------------- top-k per graph via bitonic sort (double keys) ----------
__global__ void k_topk(float* __restrict__ out_perm) {
    int g = blockIdx.x;
    int tid = threadIdx.x;
    __shared__ double sk[256];
    __shared__ int    si[256];
    sk[tid] = d_score[g*NPER + tid];
    si[tid] = tid;
    __syncthreads();
    for (int k2 = 2; k2 <= 256; k2 <<= 1) {
        for (int jj = k2 >> 1; jj > 0; jj >>= 1) {
            int ixj = tid ^ jj;
            if (ixj > tid) {
                double a = sk[tid], b = sk[ixj];
                int ia = si[tid], ib = si[ixj];
                bool aFirst = (a > b) || (a == b && ia < ib);
                bool desc = ((tid & k2) == 0);
                bool doswap = desc ? !aFirst : aFirst;
                if (doswap) { sk[tid] = b; sk[ixj] = a; si[tid] = ib; si[ixj] = ia; }
            }
            __syncthreads();
        }
    }
    if (tid < KSEL) {
        d_perm_local[g*KSEL + tid] = si[tid];
        out_perm[g*KSEL + tid] = (float)(g*NPER + si[tid]);
    }
}

// -------------- gather feat_p + attention scores --------------------------
__global__ void k_gather(const float* __restrict__ feat,
                         const float* __restrict__ att,
                         float* __restrict__ out_featp) {
    int i = blockIdx.x;
    int g = i / KSEL;
    int node = g*NPER + d_perm_local[i];
    int tid = threadIdx.x;
    const float* fr = feat + (int64_t)node * FF;
    float* orow = out_featp + (int64_t)i * FF;
    double a1 = 0.0, a2 = 0.0;
    for (int f = tid; f < FF; f += 128) {
        float v = fr[f];
        orow[f] = v;
        a1 += (double)v * (double)att[f];
        a2 += (double)v * (double)att[FF + f];
    }
    #pragma unroll
    for (int off = 16; off > 0; off >>= 1) {
        a1 += __shfl_down_sync(0xffffffffu, a1, off);
        a2 += __shfl_down_sync(0xffffffffu, a2, off);
    }
    __shared__ double s1[4], s2[4];
    int w = tid >> 5, l = tid & 31;
    if (l == 0) { s1[w] = a1; s2[w] = a2; }
    __syncthreads();
    if (tid == 0) {
        d_ssrc[i] = (float)(s1[0] + s1[1] + s1[2] + s1[3]);
        d_sdst[i] = (float)(s2[0] + s2[1] + s2[2] + s2[3]);
    }
}

// ---------------- khop: T = A@A per block + global max --------------------
// grid (NPER/64, NPER/64, BG), block 256. Same engine as aggscore.
__global__ void __launch_bounds__(256) k_mm(int iter) {
    const int g = blockIdx.z;
    const int cBase = blockIdx.x * 64;   // n
    const int rBase = blockIdx.y * 64;   // m
    const int tid = threadIdx.x, tx = tid & 15, ty = tid >> 4;
    __shared__ float As[2][16][68];
    __shared__ float Bs[2][16][68];
    const float* Ag = d_A + (g << 16);
    float* Tg = d_T + (g << 16);

    const int mA = tid >> 2, kfA = (tid & 3) * 4;
    float4 ra, rb;
    auto fetch = [&](int s) {
        int k0 = s * 16;
        ra = *(const float4*)(Ag + (rBase + mA) * 256 + k0 + kfA);
        rb = *(const float4*)(Ag + (k0 + ty) * 256 + cBase + tx * 4);
    };
    auto stash = [&](int b) {
        As[b][kfA + 0][mA] = ra.x;
        As[b][kfA + 1][mA] = ra.y;
        As[b][kfA + 2][mA] = ra.z;
        As[b][kfA + 3][mA] = ra.w;
        *(float4*)&Bs[b][ty][tx * 4] = rb;
    };

    unsigned long long acc[4][2] = {};
    fetch(0); stash(0); __syncthreads();
    #pragma unroll 1
    for (int s = 0; s < 16; s++) {
        if (s < 15) fetch(s + 1);
        int b = s & 1;
        #pragma unroll
        for (int kk = 0; kk < 16; kk++) {
            const float4 a4 = *(const float4*)&As[b][kk][ty * 4];
            const ulonglong2 b2 = *(const ulonglong2*)&Bs[b][kk][tx * 4];
            unsigned long long pa;
            pa = pack_dup(a4.x); FFMA2(acc[0][0], pa, b2.x); FFMA2(acc[0][1], pa, b2.y);
            pa = pack_dup(a4.y); FFMA2(acc[1][0], pa, b2.x); FFMA2(acc[1][1], pa, b2.y);
            pa = pack_dup(a4.z); FFMA2(acc[2][0], pa, b2.x); FFMA2(acc[2][1], pa, b2.y);
            pa = pack_dup(a4.w); FFMA2(acc[3][0], pa, b2.x); FFMA2(acc[3][1], pa, b2.y);
        }
        if (s < 15) stash((s + 1) & 1);
        __syncthreads();
    }

    float m = 0.0f;
    #pragma unroll
    for (int i = 0; i < 4; i++) {
        float2 lo = unpk(acc[i][0]);
        float2 hi = unpk(acc[i][1]);
        ulonglong2 st; st.x = acc[i][0]; st.y = acc[i][1];
        *(ulonglong2*)(Tg + (rBase + ty * 4 + i) * 256 + cBase + tx * 4) = st;
        m = fmaxf(m, fmaxf(fmaxf(lo.x, lo.y), fmaxf(hi.x, hi.y)));
    }
    #pragma unroll
    for (int off = 16; off > 0; off >>= 1)
        m = fmaxf(m, __shfl_xor_sync(0xffffffffu, m, off));
    __shared__ float smax[8];
    if ((tid & 31) == 0) smax[tid >> 5] = m;
    __syncthreads();
    if (tid == 0) {
        float mm = smax[0];
        #pragma unroll
        for (int w = 1; w < 8; w++) mm = fmaxf(mm, smax[w]);
        atomicMax((unsigned int*)&d_maxT[iter], __float_as_uint(mm));
    }
}

__global__ void k_axpy(int iter) {
    float s = 1e-5f / d_maxT[iter];
    int64_t i = (int64_t)blockIdx.x * blockDim.x + threadIdx.x;
    int64_t stride = (int64_t)gridDim.x * blockDim.x;
    for (int64_t t = i; t < (int64_t)BG*NPER*NPER; t += stride)
        d_A[t] += d_T[t] * s;
}

// ---------------- sparsemax per dst column --------------------------------
__global__ void k_sparsemax(float* __restrict__ outw) {
    int jj = blockIdx.x;
    int g  = blockIdx.y;
    int tid = threadIdx.x;
    __shared__ float zorig[256], zs[256], cs[256];

    int plj = d_perm_local[g*KSEL + jj];
    float sdstj = d_sdst[g*KSEL + jj];

    float z = -1e9f;
    bool maskv = false;
    if (tid < KSEL) {
        int pli = d_perm_local[g*KSEL + tid];
        float a = d_A[(g << 16) + (pli << 8) + plj];
        maskv = (a != 0.0f) || (tid == jj);
        if (maskv) {
            float raw = d_ssrc[g*KSEL + tid] + sdstj;
            float lr = raw > 0.0f ? raw : 0.2f * raw;
            z = lr + a;    // LAMB = 1
        }
    }
    zorig[tid] = z;
    zs[tid] = z;
    __syncthreads();

    for (int k2 = 2; k2 <= 256; k2 <<= 1) {
        for (int j2 = k2 >> 1; j2 > 0; j2 >>= 1) {
            int ixj = tid ^ j2;
            if (ixj > tid) {
                float a = zs[tid], b = zs[ixj];
                bool desc = ((tid & k2) == 0);
                if (desc ? (b > a) : (a > b)) { zs[tid] = b; zs[ixj] = a; }
            }
            __syncthreads();
        }
    }
    cs[tid] = zs[tid];
    __syncthreads();
    for (int off = 1; off < 256; off <<= 1) {
        float v = (tid >= off) ? cs[tid - off] : 0.0f;
        __syncthreads();
        cs[tid] += v;
        __syncthreads();
    }
    bool cond = (1.0f + (float)(tid + 1) * zs[tid]) > cs[tid];
    int ksel = __syncthreads_count(cond);
    float tau = (cs[ksel - 1] - 1.0f) / (float)ksel;
    if (tid < KSEL) {
        float wv = maskv ? fmaxf(zorig[tid] - tau, 0.0f) : 0.0f;
        outw[(int64_t)(g*KSEL + tid) * NK + (g*KSEL + jj)] = wv;
    }
}

// ---------------------------------------------------------------------------
extern "C" void kernel_launch(void* const* d_in, const int* in_sizes, int n_in,
                              void* d_out, int out_size) {
    const float* feat = (const float*)d_in[0];
    const float* ef   = (const float*)d_in[1];
    const float* att  = (const float*)d_in[2];
    const int*   row  = (const int*)d_in[3];
    const int*   col  = (const int*)d_in[4];
    float* out = (float*)d_out;

    k_init<<<1024, 256>>>(out);
    k_scatter<<<EE/256, 256>>>(ef, row, col);
    k_norm<<<NN/256, 256>>>();
    k_aggscore<<<dim3(FF/64, NPER/64, BG), 256>>>(feat);
    k_topk<<<BG, 256>>>(out + OUT_PERM_OFF);
    k_gather<<<NK, 128>>>(feat, att, out + OUT_FEATP_OFF);
    for (int it = 0; it < KHOP; it++) {
        k_mm<<<dim3(NPER/64, NPER/64, BG), 256>>>(it);
        k_axpy<<<512, 256>>>(it);
    }
    k_sparsemax<<<dim3(KSEL, BG), 256>>>(out + OUT_W_OFF);
}